// round 7
// baseline (speedup 1.0000x reference)
#include <cuda_runtime.h>
#include <cstdint>
#include <math.h>

// Problem constants
#define BATCH 16
#define DIMC  512
#define NPTS  4096

// ---------------------------------------------------------------------------
// Packed split layout ("pk"): for each logical row (length K), floats are
// stored as K/32 blocks of 64 floats. Within a 32-k block, for k = 8s+tig+4h
// (s,tig in 0..3, h in 0..1):  chunk cc = s*4+tig (16B), contents
// (hi(k), lo(k), hi(k+4), lo(k+4)).  Row-block stride = 2*K floats.
// ---------------------------------------------------------------------------
__device__ float g_xpk [BATCH * DIMC * 2 * NPTS];   // rows=dim, K=N
__device__ float g_xTpk[BATCH * NPTS * 2 * DIMC];   // rows=N,  K=dim
__device__ float g_Wqpk [DIMC * 2 * DIMC];
__device__ float g_Wkpk [DIMC * 2 * DIMC];
__device__ float g_WvTpk[DIMC * 2 * DIMC];
__device__ float g_Gpk[BATCH * DIMC * 2 * DIMC];
__device__ float g_Tpk[BATCH * DIMC * 2 * DIMC];
__device__ float g_Spk[BATCH * DIMC * 2 * DIMC];
__device__ float g_Mpk[BATCH * DIMC * 2 * DIMC];
__device__ float g_S  [BATCH * DIMC * DIMC];        // plain logits

// ===========================================================================
// Helpers
// ===========================================================================
__device__ __forceinline__ uint32_t f2tf32(float x) {
    uint32_t r;
    asm("cvt.rna.tf32.f32 %0, %1;" : "=r"(r) : "f"(x));
    return r;
}
__device__ __forceinline__ void tf32_split(float v, float& hi, float& lo) {
    hi = __uint_as_float(f2tf32(v));
    lo = __uint_as_float(f2tf32(v - hi));
}

#define CP_ASYNC16(saddr, gptr) \
    asm volatile("cp.async.cg.shared.global [%0], [%1], 16;" \
        :: "r"(saddr), "l"(gptr) : "memory")
#define CP_COMMIT()  asm volatile("cp.async.commit_group;" ::: "memory")
#define CP_WAIT(n)   asm volatile("cp.async.wait_group %0;" :: "n"(n) : "memory")

__device__ __forceinline__ uint32_t smem_u32(const void* p) {
    uint32_t a;
    asm("{ .reg .u64 t; cvta.to.shared.u64 t, %1; cvt.u32.u64 %0, t; }"
        : "=r"(a) : "l"(p));
    return a;
}

__device__ __forceinline__ void mma_tf32(
    float c[4], uint32_t a0, uint32_t a1, uint32_t a2, uint32_t a3,
    uint32_t b0, uint32_t b1)
{
    asm volatile(
        "mma.sync.aligned.m16n8k8.row.col.f32.tf32.tf32.f32 "
        "{%0,%1,%2,%3}, {%4,%5,%6,%7}, {%8,%9}, {%0,%1,%2,%3};"
        : "+f"(c[0]), "+f"(c[1]), "+f"(c[2]), "+f"(c[3])
        : "r"(a0), "r"(a1), "r"(a2), "r"(a3), "r"(b0), "r"(b1));
}

// Packed split store: (hi,lo) are adjacent by construction -> one float2.
__device__ __forceinline__ void st_split_pk(float* Cpk, long long rowbase,
                                            int col, float v)
{
    const int kt = col >> 5, kk = col & 31;
    const int s = kk >> 3, tg = kk & 3, h = (kk >> 2) & 1;
    float hi, lo;
    tf32_split(v, hi, lo);
    *(float2*)(Cpk + rowbase + kt * 64 + (s * 4 + tg) * 4 + 2 * h) =
        make_float2(hi, lo);
}

// ===========================================================================
// 3xTF32 NT GEMM on PACKED pre-split operands.
//   C[m][n] = alpha * sum_k A[m][k]*B[n][k]; acc += Al*Bh + Ah*Bl + Ah*Bh
// CTA tile 128x128, BK=32, 8 warps 2(m)x4(n), warp tile 64x32.
// One LDS.128 per fragment-row (4 floats = hi/lo of k,k+4).
// 2-stage cp.async pipeline. All dims divide tiles exactly.
// ===========================================================================
#define BM 128
#define BN 128
#define PITCH 80                              // floats per smem row (20 chunks)
#define ATILE_FLOATS (128 * PITCH)            // 10240 floats (40960 B)
#define STAGE_FLOATS (2 * ATILE_FLOATS)       // A + B
#define SMEM_FLOATS (2 * STAGE_FLOATS)        // 2 stages
#define SMEM_BYTES (SMEM_FLOATS * 4)          // 163840

__global__ __launch_bounds__(256) void gemm3p_nt(
    const float* __restrict__ Apk, const float* __restrict__ Bpk,
    float* __restrict__ Cp, float* __restrict__ Cpk,
    int K, int ldA2, int ldB2, int ldc, int ldcp,
    long long sA, long long sB, long long sC, long long sCp, float alpha)
{
    extern __shared__ float smem[];
    const int tid  = threadIdx.x;
    const int wid  = tid >> 5;
    const int lane = tid & 31;
    const int wm   = wid & 1;
    const int wn   = wid >> 1;

    Apk += blockIdx.z * sA + (long long)(blockIdx.y * BM) * ldA2;
    Bpk += blockIdx.z * sB + (long long)(blockIdx.x * BN) * ldB2;

    const uint32_t smem_base = smem_u32(smem);

    float acc[4][4][4];
#pragma unroll
    for (int i = 0; i < 4; i++)
#pragma unroll
        for (int j = 0; j < 4; j++)
#pragma unroll
            for (int r = 0; r < 4; r++) acc[i][j][r] = 0.0f;

    const int ktiles = K / 32;

    // Issue one k-tile: 2048 16B chunks per operand; 256 threads x 8 each.
    auto issue_tile = [&](int kt, int st) {
        const uint32_t s0 = smem_base + (uint32_t)(st * STAGE_FLOATS) * 4u;
#pragma unroll
        for (int p = 0; p < 8; ++p) {
            const int c   = tid + p * 256;   // 0..2047
            const int row = c >> 4;
            const int cc  = c & 15;
            const uint32_t so = (uint32_t)(row * PITCH + cc * 4) * 4u;
            CP_ASYNC16(s0 + so,
                       Apk + (long long)row * ldA2 + kt * 64 + cc * 4);
            CP_ASYNC16(s0 + (uint32_t)ATILE_FLOATS * 4u + so,
                       Bpk + (long long)row * ldB2 + kt * 64 + cc * 4);
        }
        CP_COMMIT();
    };

    issue_tile(0, 0);
    if (ktiles > 1) issue_tile(1, 1);

    const int gid = lane >> 2;
    const int tig = lane & 3;

    for (int kt = 0; kt < ktiles; ++kt) {
        const int st = kt & 1;
        if (kt + 1 < ktiles) { CP_WAIT(1); } else { CP_WAIT(0); }
        __syncthreads();

        const float* Ash = smem + st * STAGE_FLOATS;
        const float* Bsh = Ash + ATILE_FLOATS;

#pragma unroll
        for (int s = 0; s < 4; ++s) {
            const int off = (s * 4 + tig) * 4;
            float4 av0[4], av1[4], bv[4];
#pragma unroll
            for (int fi = 0; fi < 4; ++fi) {
                const int r = wm * 64 + fi * 16 + gid;
                av0[fi] = *(const float4*)(Ash + r * PITCH + off);
                av1[fi] = *(const float4*)(Ash + (r + 8) * PITCH + off);
            }
#pragma unroll
            for (int fj = 0; fj < 4; ++fj) {
                const int n = wn * 32 + fj * 8 + gid;
                bv[fj] = *(const float4*)(Bsh + n * PITCH + off);
            }
#pragma unroll
            for (int fi = 0; fi < 4; ++fi) {
                const uint32_t ah0 = __float_as_uint(av0[fi].x);
                const uint32_t ah1 = __float_as_uint(av1[fi].x);
                const uint32_t ah2 = __float_as_uint(av0[fi].z);
                const uint32_t ah3 = __float_as_uint(av1[fi].z);
                const uint32_t al0 = __float_as_uint(av0[fi].y);
                const uint32_t al1 = __float_as_uint(av1[fi].y);
                const uint32_t al2 = __float_as_uint(av0[fi].w);
                const uint32_t al3 = __float_as_uint(av1[fi].w);
#pragma unroll
                for (int fj = 0; fj < 4; ++fj) {
                    const uint32_t bh0 = __float_as_uint(bv[fj].x);
                    const uint32_t bh1 = __float_as_uint(bv[fj].z);
                    const uint32_t bl0 = __float_as_uint(bv[fj].y);
                    const uint32_t bl1 = __float_as_uint(bv[fj].w);
                    mma_tf32(acc[fi][fj], al0, al1, al2, al3, bh0, bh1);
                    mma_tf32(acc[fi][fj], ah0, ah1, ah2, ah3, bl0, bl1);
                    mma_tf32(acc[fi][fj], ah0, ah1, ah2, ah3, bh0, bh1);
                }
            }
        }
        __syncthreads();
        if (kt + 2 < ktiles) issue_tile(kt + 2, st);
    }

    // Epilogue
    const int crow0 = blockIdx.y * BM + wm * 64 + gid;
    const int ccol0 = blockIdx.x * BN + wn * 32 + 2 * tig;
#pragma unroll
    for (int fi = 0; fi < 4; ++fi) {
#pragma unroll
        for (int fj = 0; fj < 4; ++fj) {
            const int r0 = crow0 + fi * 16;
            const int c0 = ccol0 + fj * 8;
            const float v0 = acc[fi][fj][0] * alpha;
            const float v1 = acc[fi][fj][1] * alpha;
            const float v2 = acc[fi][fj][2] * alpha;
            const float v3 = acc[fi][fj][3] * alpha;
            if (Cp) {
                const long long e0 = blockIdx.z * sC + (long long)r0 * ldc + c0;
                *(float2*)(Cp + e0)           = make_float2(v0, v1);
                *(float2*)(Cp + e0 + 8 * ldc) = make_float2(v2, v3);
            }
            if (Cpk) {
                const long long b0 = blockIdx.z * sCp + (long long)r0 * ldcp;
                const long long b1 = b0 + 8LL * ldcp;
                st_split_pk(Cpk, b0, c0,     v0);
                st_split_pk(Cpk, b0, c0 + 1, v1);
                st_split_pk(Cpk, b1, c0,     v2);
                st_split_pk(Cpk, b1, c0 + 1, v3);
            }
        }
    }
}

// ===========================================================================
// Split+pack kernel: 32x32 tile; writes packed straight (oPk) and/or packed
// transposed (oTPk). Chunk writes are fully coalesced float4s.
// ===========================================================================
__global__ __launch_bounds__(256) void split_pack_kernel(
    const float* __restrict__ in,
    float* __restrict__ oPk, float* __restrict__ oTPk,
    int rows, int cols, long long sin, long long soP, long long soT)
{
    __shared__ float hi[32][33], lo[32][33];
    const float* I = in + (long long)blockIdx.z * sin;
    const int c0 = blockIdx.x * 32;
    const int r0 = blockIdx.y * 32;
    const int tx = threadIdx.x & 31, ty = threadIdx.x >> 5;

#pragma unroll
    for (int i = ty; i < 32; i += 8) {
        const float v = I[(long long)(r0 + i) * cols + c0 + tx];
        tf32_split(v, hi[i][tx], lo[i][tx]);
    }
    __syncthreads();

    // 512 chunks per output: q -> (row i = q>>4, chunk cc = q&15)
    if (oPk) {
        float* O = oPk + blockIdx.z * soP;
#pragma unroll
        for (int p = 0; p < 2; ++p) {
            const int q  = threadIdx.x + p * 256;
            const int i  = q >> 4, cc = q & 15;
            const int s  = cc >> 2, tg = cc & 3;
            const int k1 = 8 * s + tg, k2 = k1 + 4;
            float4 w = make_float4(hi[i][k1], lo[i][k1], hi[i][k2], lo[i][k2]);
            *(float4*)(O + (long long)(r0 + i) * (2LL * cols)
                         + (c0 >> 5) * 64 + cc * 4) = w;
        }
    }
    if (oTPk) {
        float* O = oTPk + blockIdx.z * soT;
#pragma unroll
        for (int p = 0; p < 2; ++p) {
            const int q  = threadIdx.x + p * 256;
            const int i  = q >> 4, cc = q & 15;
            const int s  = cc >> 2, tg = cc & 3;
            const int k1 = 8 * s + tg, k2 = k1 + 4;
            float4 w = make_float4(hi[k1][i], lo[k1][i], hi[k2][i], lo[k2][i]);
            *(float4*)(O + (long long)(c0 + i) * (2LL * rows)
                         + (r0 >> 5) * 64 + cc * 4) = w;
        }
    }
}

// ===========================================================================
// Row softmax over S (plain in), writing PACKED split output.
// ===========================================================================
__global__ __launch_bounds__(256) void softmax_pack_kernel(
    const float* __restrict__ S, float* __restrict__ Spk)
{
    __shared__ float red[8];
    __shared__ float sm[DIMC];
    const long long row = blockIdx.x;
    const float* p = S + row * DIMC;
    const int t = threadIdx.x;
    const int lane = t & 31, warp = t >> 5;

    float v0 = p[t];
    float v1 = p[t + 256];

    float m = fmaxf(v0, v1);
#pragma unroll
    for (int o = 16; o; o >>= 1) m = fmaxf(m, __shfl_xor_sync(0xFFFFFFFFu, m, o));
    if (lane == 0) red[warp] = m;
    __syncthreads();
    m = red[0];
#pragma unroll
    for (int w = 1; w < 8; ++w) m = fmaxf(m, red[w]);
    __syncthreads();

    const float e0 = expf(v0 - m);
    const float e1 = expf(v1 - m);
    float sum = e0 + e1;
#pragma unroll
    for (int o = 16; o; o >>= 1) sum += __shfl_xor_sync(0xFFFFFFFFu, sum, o);
    if (lane == 0) red[warp] = sum;
    __syncthreads();
    sum = red[0];
#pragma unroll
    for (int w = 1; w < 8; ++w) sum += red[w];
    const float inv = 1.0f / sum;

    sm[t]       = e0 * inv;
    sm[t + 256] = e1 * inv;
    __syncthreads();

    // 256 chunks per row (512 cols / 2 per chunk); one chunk per thread.
    const int ktile = t >> 4, cc = t & 15;
    const int s = cc >> 2, tg = cc & 3;
    const int k1 = ktile * 32 + 8 * s + tg, k2 = k1 + 4;
    float h1, l1, h2, l2;
    tf32_split(sm[k1], h1, l1);
    tf32_split(sm[k2], h2, l2);
    *(float4*)(Spk + row * (2LL * DIMC) + t * 4) = make_float4(h1, l1, h2, l2);
}

// ===========================================================================
// Launch chain (all GEMMs NT, packed pre-split 3xTF32):
//   pack x -> xpk + xTpk;  pack Wq, Wk;  pack-T Wv
//   G = x.x^T (K=4096)        -> Gpk
//   T = Wq.G  (G symmetric)   -> Tpk
//   S = (1/tau) T.Wk^T        -> S plain
//   softmax(S)                -> Spk
//   M = A.Wv  (via WvT)       -> Mpk
//   out = M.x (via xT)        -> out plain
// ===========================================================================
extern "C" void kernel_launch(void* const* d_in, const int* in_sizes, int n_in,
                              void* d_out, int out_size)
{
    const float* x  = (const float*)d_in[0];
    const float* Wq = (const float*)d_in[1];
    const float* Wk = (const float*)d_in[2];
    const float* Wv = (const float*)d_in[3];
    float* out = (float*)d_out;

    float *xpk, *xTpk, *Wqpk, *Wkpk, *WvTpk, *Gpk, *Tpk, *Spk, *Mpk, *S;
    cudaGetSymbolAddress((void**)&xpk,   g_xpk);
    cudaGetSymbolAddress((void**)&xTpk,  g_xTpk);
    cudaGetSymbolAddress((void**)&Wqpk,  g_Wqpk);
    cudaGetSymbolAddress((void**)&Wkpk,  g_Wkpk);
    cudaGetSymbolAddress((void**)&WvTpk, g_WvTpk);
    cudaGetSymbolAddress((void**)&Gpk,   g_Gpk);
    cudaGetSymbolAddress((void**)&Tpk,   g_Tpk);
    cudaGetSymbolAddress((void**)&Spk,   g_Spk);
    cudaGetSymbolAddress((void**)&Mpk,   g_Mpk);
    cudaGetSymbolAddress((void**)&S,     g_S);

    cudaFuncSetAttribute(gemm3p_nt,
                         cudaFuncAttributeMaxDynamicSharedMemorySize, SMEM_BYTES);

    const long long sX   = (long long)DIMC * NPTS;        // plain x batch stride
    const long long sXpk = (long long)DIMC * 2 * NPTS;    // packed x batch stride
    const long long sXT  = (long long)NPTS * 2 * DIMC;    // packed xT batch stride
    const long long sDD  = (long long)DIMC * DIMC;        // plain square stride
    const long long sDDp = (long long)DIMC * 2 * DIMC;    // packed square stride
    const float inv_tau  = (float)(1.0 / sqrt((double)DIMC));

    // Packs
    {
        dim3 gx(NPTS / 32, DIMC / 32, BATCH);
        split_pack_kernel<<<gx, 256>>>(x, xpk, xTpk, DIMC, NPTS, sX, sXpk, sXT);
        dim3 gw(DIMC / 32, DIMC / 32, 1);
        split_pack_kernel<<<gw, 256>>>(Wq, Wqpk, nullptr, DIMC, DIMC, 0, 0, 0);
        split_pack_kernel<<<gw, 256>>>(Wk, Wkpk, nullptr, DIMC, DIMC, 0, 0, 0);
        split_pack_kernel<<<gw, 256>>>(Wv, nullptr, WvTpk, DIMC, DIMC, 0, 0, 0);
    }

    dim3 gSq(DIMC / BN, DIMC / BM, BATCH);   // 4 x 4 x 16
    dim3 gOut(NPTS / BN, DIMC / BM, BATCH);  // 32 x 4 x 16

    // G[b] = x[b] . x[b]^T  -> packed
    gemm3p_nt<<<gSq, 256, SMEM_BYTES>>>(xpk, xpk, nullptr, Gpk,
        NPTS, 2 * NPTS, 2 * NPTS, DIMC, 2 * DIMC,
        sXpk, sXpk, 0LL, sDDp, 1.0f);

    // T[b] = Wq . G[b]  (G symmetric) -> packed
    gemm3p_nt<<<gSq, 256, SMEM_BYTES>>>(Wqpk, Gpk, nullptr, Tpk,
        DIMC, 2 * DIMC, 2 * DIMC, DIMC, 2 * DIMC,
        0LL, sDDp, 0LL, sDDp, 1.0f);

    // S[b] = (1/tau) T[b] . Wk^T -> plain
    gemm3p_nt<<<gSq, 256, SMEM_BYTES>>>(Tpk, Wkpk, S, nullptr,
        DIMC, 2 * DIMC, 2 * DIMC, DIMC, 2 * DIMC,
        sDDp, 0LL, sDD, 0LL, inv_tau);

    // softmax -> packed
    softmax_pack_kernel<<<BATCH * DIMC, 256>>>(S, Spk);

    // M[b] = A[b] . Wv (B = WvT) -> packed
    gemm3p_nt<<<gSq, 256, SMEM_BYTES>>>(Spk, WvTpk, nullptr, Mpk,
        DIMC, 2 * DIMC, 2 * DIMC, DIMC, 2 * DIMC,
        sDDp, 0LL, 0LL, sDDp, 1.0f);

    // out[b] = M[b] . x[b]  (B = xT) -> plain
    gemm3p_nt<<<gOut, 256, SMEM_BYTES>>>(Mpk, xTpk, out, nullptr,
        DIMC, 2 * DIMC, 2 * DIMC, NPTS, 2 * DIMC,
        sDDp, sXT, sX, 0LL, 1.0f);
}

// round 8
// speedup vs baseline: 1.4557x; 1.4557x over previous
#include <cuda_runtime.h>
#include <cuda_bf16.h>
#include <cstdint>
#include <math.h>

// Problem constants
#define BATCH 16
#define DIMC  512
#define NPTS  4096

// ---------------------------------------------------------------------------
// Scratch: bf16 split pairs (hi = rn(v), lo = rn(v - hi)), plain K-major.
// ---------------------------------------------------------------------------
__device__ __nv_bfloat16 g_xh [BATCH * DIMC * NPTS];
__device__ __nv_bfloat16 g_xl [BATCH * DIMC * NPTS];
__device__ __nv_bfloat16 g_xTh[BATCH * NPTS * DIMC];
__device__ __nv_bfloat16 g_xTl[BATCH * NPTS * DIMC];
__device__ __nv_bfloat16 g_Wqh[DIMC * DIMC];
__device__ __nv_bfloat16 g_Wql[DIMC * DIMC];
__device__ __nv_bfloat16 g_Wkh[DIMC * DIMC];
__device__ __nv_bfloat16 g_Wkl[DIMC * DIMC];
__device__ __nv_bfloat16 g_WvTh[DIMC * DIMC];
__device__ __nv_bfloat16 g_WvTl[DIMC * DIMC];
__device__ __nv_bfloat16 g_Gh[BATCH * DIMC * DIMC];
__device__ __nv_bfloat16 g_Gl[BATCH * DIMC * DIMC];
__device__ __nv_bfloat16 g_Th[BATCH * DIMC * DIMC];
__device__ __nv_bfloat16 g_Tl[BATCH * DIMC * DIMC];
__device__ __nv_bfloat16 g_Ah[BATCH * DIMC * DIMC];
__device__ __nv_bfloat16 g_Al[BATCH * DIMC * DIMC];
__device__ __nv_bfloat16 g_Mh[BATCH * DIMC * DIMC];
__device__ __nv_bfloat16 g_Ml[BATCH * DIMC * DIMC];
__device__ float g_S[BATCH * DIMC * DIMC];           // plain logits

// ===========================================================================
// Helpers
// ===========================================================================
__device__ __forceinline__ void bf16_split(float v, __nv_bfloat16& h, __nv_bfloat16& l) {
    h = __float2bfloat16_rn(v);
    l = __float2bfloat16_rn(v - __bfloat162float(h));
}
__device__ __forceinline__ uint32_t pack2(__nv_bfloat16 a, __nv_bfloat16 b) {
    uint16_t ua, ub;
    memcpy(&ua, &a, 2); memcpy(&ub, &b, 2);
    return (uint32_t)ua | ((uint32_t)ub << 16);
}

#define CP_ASYNC16(saddr, gptr) \
    asm volatile("cp.async.cg.shared.global [%0], [%1], 16;" \
        :: "r"(saddr), "l"(gptr) : "memory")
#define CP_COMMIT()  asm volatile("cp.async.commit_group;" ::: "memory")
#define CP_WAIT(n)   asm volatile("cp.async.wait_group %0;" :: "n"(n) : "memory")

__device__ __forceinline__ uint32_t smem_u32(const void* p) {
    uint32_t a;
    asm("{ .reg .u64 t; cvta.to.shared.u64 t, %1; cvt.u32.u64 %0, t; }"
        : "=r"(a) : "l"(p));
    return a;
}

__device__ __forceinline__ void mma_bf16(
    float c[4], uint32_t a0, uint32_t a1, uint32_t a2, uint32_t a3,
    uint32_t b0, uint32_t b1)
{
    asm volatile(
        "mma.sync.aligned.m16n8k16.row.col.f32.bf16.bf16.f32 "
        "{%0,%1,%2,%3}, {%4,%5,%6,%7}, {%8,%9}, {%0,%1,%2,%3};"
        : "+f"(c[0]), "+f"(c[1]), "+f"(c[2]), "+f"(c[3])
        : "r"(a0), "r"(a1), "r"(a2), "r"(a3), "r"(b0), "r"(b1));
}

// ===========================================================================
// bf16x2-split NT GEMM:  C[m][n] = alpha * sum_k A[m][k]*B[n][k]
//   A = Ah+Al, B = Bh+Bl (bf16); acc += Al*Bh + Ah*Bl + Ah*Bh.
// CTA tile 128x128, BK=32 (2 x k16 HMMA steps), 8 warps 2(m)x4(n),
// warp tile 64x32. 3-stage cp.async pipeline.
// SMEM row = 32 bf16 (64B) padded to 80B -> LDS.32 frag loads conflict-free.
// ===========================================================================
#define BM 128
#define BN 128
#define PITCHB 80                          // bytes per 32-element bf16 row
#define TILE_BYTES (128 * PITCHB)          // 10240 per operand array
#define STAGE_BYTES (4 * TILE_BYTES)       // Ah, Al, Bh, Bl = 40960
#define NSTAGE 3
#define SMEM_BYTES (NSTAGE * STAGE_BYTES)  // 122880

__global__ __launch_bounds__(256) void gemm_bf16x2_nt(
    const __nv_bfloat16* __restrict__ Ah, const __nv_bfloat16* __restrict__ Al,
    const __nv_bfloat16* __restrict__ Bh, const __nv_bfloat16* __restrict__ Bl,
    float* __restrict__ Cp, __nv_bfloat16* __restrict__ Ch, __nv_bfloat16* __restrict__ Cl,
    int K, int lda, int ldb, int ldc, int ldcp,
    long long sA, long long sB, long long sC, long long sCp, float alpha)
{
    extern __shared__ char smem[];
    const int tid  = threadIdx.x;
    const int wid  = tid >> 5;
    const int lane = tid & 31;
    const int wm   = wid & 1;
    const int wn   = wid >> 1;

    const long long offA = blockIdx.z * sA + (long long)(blockIdx.y * BM) * lda;
    const long long offB = blockIdx.z * sB + (long long)(blockIdx.x * BN) * ldb;
    Ah += offA; Al += offA;
    Bh += offB; Bl += offB;

    const uint32_t smem_base = smem_u32(smem);

    float acc[4][4][4];
#pragma unroll
    for (int i = 0; i < 4; i++)
#pragma unroll
        for (int j = 0; j < 4; j++)
#pragma unroll
            for (int r = 0; r < 4; r++) acc[i][j][r] = 0.0f;

    const int ktiles = K / 32;

    // Loader: row-per-lane mapping; 8-lane phases hit distinct 16B bank
    // groups ((row*5 + ch) mod 8 all distinct). 8 cp.async per thread.
    const int l_row = tid & 127;
    const int l_ch0 = (tid >> 7) * 2;
    auto issue_tile = [&](int kt, int st) {
        const uint32_t s0 = smem_base + (uint32_t)(st * STAGE_BYTES);
        const __nv_bfloat16* pAh = Ah + (long long)l_row * lda + kt * 32;
        const __nv_bfloat16* pAl = Al + (long long)l_row * lda + kt * 32;
        const __nv_bfloat16* pBh = Bh + (long long)l_row * ldb + kt * 32;
        const __nv_bfloat16* pBl = Bl + (long long)l_row * ldb + kt * 32;
#pragma unroll
        for (int p = 0; p < 2; ++p) {
            const int ch = l_ch0 + p;
            const uint32_t so = (uint32_t)(l_row * PITCHB + ch * 16);
            CP_ASYNC16(s0 + so,                  pAh + ch * 8);
            CP_ASYNC16(s0 + TILE_BYTES + so,     pAl + ch * 8);
            CP_ASYNC16(s0 + 2 * TILE_BYTES + so, pBh + ch * 8);
            CP_ASYNC16(s0 + 3 * TILE_BYTES + so, pBl + ch * 8);
        }
        CP_COMMIT();
    };

    issue_tile(0, 0);
    if (ktiles > 1) issue_tile(1, 1);

    const int gid = lane >> 2;
    const int tig = lane & 3;

    for (int kt = 0; kt < ktiles; ++kt) {
        const int st = kt % NSTAGE;
        if (kt == ktiles - 1) { CP_WAIT(0); } else { CP_WAIT(1); }
        __syncthreads();
        if (kt + 2 < ktiles) issue_tile(kt + 2, (kt + 2) % NSTAGE);

        const char* Ash = smem + st * STAGE_BYTES;
        const char* Asl = Ash + TILE_BYTES;
        const char* Bsh = Asl + TILE_BYTES;
        const char* Bsl = Bsh + TILE_BYTES;

#pragma unroll
        for (int s = 0; s < 2; ++s) {          // 2 x k16 steps
            const int ko = s * 32 + 4 * tig;   // byte offset within row
            uint32_t ah[4][4], al[4][4];
#pragma unroll
            for (int fi = 0; fi < 4; ++fi) {
                const int r = wm * 64 + fi * 16 + gid;
                const char* ph = Ash + r * PITCHB + ko;
                const char* pl = Asl + r * PITCHB + ko;
                ah[fi][0] = *(const uint32_t*)(ph);
                ah[fi][1] = *(const uint32_t*)(ph + 8 * PITCHB);
                ah[fi][2] = *(const uint32_t*)(ph + 16);
                ah[fi][3] = *(const uint32_t*)(ph + 8 * PITCHB + 16);
                al[fi][0] = *(const uint32_t*)(pl);
                al[fi][1] = *(const uint32_t*)(pl + 8 * PITCHB);
                al[fi][2] = *(const uint32_t*)(pl + 16);
                al[fi][3] = *(const uint32_t*)(pl + 8 * PITCHB + 16);
            }
            uint32_t bh[4][2], bl[4][2];
#pragma unroll
            for (int fj = 0; fj < 4; ++fj) {
                const int n = wn * 32 + fj * 8 + gid;
                const char* ph = Bsh + n * PITCHB + ko;
                const char* pl = Bsl + n * PITCHB + ko;
                bh[fj][0] = *(const uint32_t*)(ph);
                bh[fj][1] = *(const uint32_t*)(ph + 16);
                bl[fj][0] = *(const uint32_t*)(pl);
                bl[fj][1] = *(const uint32_t*)(pl + 16);
            }
#pragma unroll
            for (int fi = 0; fi < 4; ++fi)
#pragma unroll
                for (int fj = 0; fj < 4; ++fj) {
                    mma_bf16(acc[fi][fj], al[fi][0], al[fi][1], al[fi][2], al[fi][3],
                             bh[fj][0], bh[fj][1]);
                    mma_bf16(acc[fi][fj], ah[fi][0], ah[fi][1], ah[fi][2], ah[fi][3],
                             bl[fj][0], bl[fj][1]);
                    mma_bf16(acc[fi][fj], ah[fi][0], ah[fi][1], ah[fi][2], ah[fi][3],
                             bh[fj][0], bh[fj][1]);
                }
        }
    }

    // Epilogue
    const int crow0 = blockIdx.y * BM + wm * 64 + gid;
    const int ccol0 = blockIdx.x * BN + wn * 32 + 2 * tig;
#pragma unroll
    for (int fi = 0; fi < 4; ++fi) {
#pragma unroll
        for (int fj = 0; fj < 4; ++fj) {
            const int r0 = crow0 + fi * 16;
            const int c0 = ccol0 + fj * 8;
            const float v0 = acc[fi][fj][0] * alpha;
            const float v1 = acc[fi][fj][1] * alpha;
            const float v2 = acc[fi][fj][2] * alpha;
            const float v3 = acc[fi][fj][3] * alpha;
            if (Cp) {
                const long long e0 = blockIdx.z * sC + (long long)r0 * ldc + c0;
                *(float2*)(Cp + e0)           = make_float2(v0, v1);
                *(float2*)(Cp + e0 + 8 * ldc) = make_float2(v2, v3);
            }
            if (Ch) {
                const long long e0 = blockIdx.z * sCp + (long long)r0 * ldcp + c0;
                const long long e1 = e0 + 8LL * ldcp;
                __nv_bfloat16 h0, l0, h1, l1, h2, l2, h3, l3;
                bf16_split(v0, h0, l0); bf16_split(v1, h1, l1);
                bf16_split(v2, h2, l2); bf16_split(v3, h3, l3);
                *(uint32_t*)(Ch + e0) = pack2(h0, h1);
                *(uint32_t*)(Cl + e0) = pack2(l0, l1);
                *(uint32_t*)(Ch + e1) = pack2(h2, h3);
                *(uint32_t*)(Cl + e1) = pack2(l2, l3);
            }
        }
    }
}

// ===========================================================================
// Split kernel: 32x32 tile -> bf16 hi/lo, straight (oH/oL) and/or
// transposed (oTH/oTL). All nullable.
// ===========================================================================
__global__ __launch_bounds__(256) void split_bf16_kernel(
    const float* __restrict__ in,
    __nv_bfloat16* __restrict__ oH,  __nv_bfloat16* __restrict__ oL,
    __nv_bfloat16* __restrict__ oTH, __nv_bfloat16* __restrict__ oTL,
    int rows, int cols, long long sin, long long so, long long soT)
{
    __shared__ __nv_bfloat16 hi[32][34], lo[32][34];
    const float* I = in + (long long)blockIdx.z * sin;
    const int c0 = blockIdx.x * 32;
    const int r0 = blockIdx.y * 32;
    const int tx = threadIdx.x & 31, ty = threadIdx.x >> 5;

#pragma unroll
    for (int i = ty; i < 32; i += 8) {
        const float v = I[(long long)(r0 + i) * cols + c0 + tx];
        bf16_split(v, hi[i][tx], lo[i][tx]);
    }
    __syncthreads();

    const int i0 = threadIdx.x >> 4;       // 0..15
    const int cp = threadIdx.x & 15;       // column pair
    if (oH) {
#pragma unroll
        for (int p = 0; p < 2; ++p) {
            const int i = i0 + p * 16;
            const long long e = (long long)blockIdx.z * so
                              + (long long)(r0 + i) * cols + c0 + 2 * cp;
            *(uint32_t*)(oH + e) = pack2(hi[i][2 * cp], hi[i][2 * cp + 1]);
            *(uint32_t*)(oL + e) = pack2(lo[i][2 * cp], lo[i][2 * cp + 1]);
        }
    }
    if (oTH) {
#pragma unroll
        for (int p = 0; p < 2; ++p) {
            const int i = i0 + p * 16;
            const long long e = (long long)blockIdx.z * soT
                              + (long long)(c0 + i) * rows + r0 + 2 * cp;
            *(uint32_t*)(oTH + e) = pack2(hi[2 * cp][i], hi[2 * cp + 1][i]);
            *(uint32_t*)(oTL + e) = pack2(lo[2 * cp][i], lo[2 * cp + 1][i]);
        }
    }
}

// ===========================================================================
// Row softmax over S (fp32), writing bf16-split A = softmax(S).
// ===========================================================================
__global__ __launch_bounds__(256) void softmax_split_kernel(
    const float* __restrict__ S,
    __nv_bfloat16* __restrict__ AH, __nv_bfloat16* __restrict__ AL)
{
    __shared__ float red[8];
    const long long row = blockIdx.x;
    const float* p = S + row * DIMC;
    const int t = threadIdx.x;
    const int lane = t & 31, warp = t >> 5;

    const float v0 = p[2 * t];
    const float v1 = p[2 * t + 1];

    float m = fmaxf(v0, v1);
#pragma unroll
    for (int o = 16; o; o >>= 1) m = fmaxf(m, __shfl_xor_sync(0xFFFFFFFFu, m, o));
    if (lane == 0) red[warp] = m;
    __syncthreads();
    m = red[0];
#pragma unroll
    for (int w = 1; w < 8; ++w) m = fmaxf(m, red[w]);
    __syncthreads();

    const float e0 = expf(v0 - m);
    const float e1 = expf(v1 - m);
    float sum = e0 + e1;
#pragma unroll
    for (int o = 16; o; o >>= 1) sum += __shfl_xor_sync(0xFFFFFFFFu, sum, o);
    if (lane == 0) red[warp] = sum;
    __syncthreads();
    sum = red[0];
#pragma unroll
    for (int w = 1; w < 8; ++w) sum += red[w];
    const float inv = 1.0f / sum;

    __nv_bfloat16 h0, l0, h1, l1;
    bf16_split(e0 * inv, h0, l0);
    bf16_split(e1 * inv, h1, l1);
    *(uint32_t*)(AH + row * DIMC + 2 * t) = pack2(h0, h1);
    *(uint32_t*)(AL + row * DIMC + 2 * t) = pack2(l0, l1);
}

// ===========================================================================
// Launch chain (all GEMMs NT, bf16x2-split HMMA.16816):
//   split x -> xh/xl + xTh/xTl; split Wq, Wk; split-T Wv
//   G = x.x^T (K=4096)      -> Gh/Gl
//   T = Wq.G (G symmetric)  -> Th/Tl
//   S = (1/tau) T.Wk^T      -> S plain
//   A = softmax(S)          -> Ah/Al
//   M = A.Wv (via WvT)      -> Mh/Ml
//   out = M.x (via xT)      -> plain
// ===========================================================================
extern "C" void kernel_launch(void* const* d_in, const int* in_sizes, int n_in,
                              void* d_out, int out_size)
{
    const float* x  = (const float*)d_in[0];
    const float* Wq = (const float*)d_in[1];
    const float* Wk = (const float*)d_in[2];
    const float* Wv = (const float*)d_in[3];
    float* out = (float*)d_out;

    __nv_bfloat16 *xh, *xl, *xTh, *xTl, *Wqh, *Wql, *Wkh, *Wkl, *WvTh, *WvTl;
    __nv_bfloat16 *Gh, *Gl, *Th, *Tl, *Ahp, *Alp, *Mh, *Ml;
    float* S;
    cudaGetSymbolAddress((void**)&xh,   g_xh);
    cudaGetSymbolAddress((void**)&xl,   g_xl);
    cudaGetSymbolAddress((void**)&xTh,  g_xTh);
    cudaGetSymbolAddress((void**)&xTl,  g_xTl);
    cudaGetSymbolAddress((void**)&Wqh,  g_Wqh);
    cudaGetSymbolAddress((void**)&Wql,  g_Wql);
    cudaGetSymbolAddress((void**)&Wkh,  g_Wkh);
    cudaGetSymbolAddress((void**)&Wkl,  g_Wkl);
    cudaGetSymbolAddress((void**)&WvTh, g_WvTh);
    cudaGetSymbolAddress((void**)&WvTl, g_WvTl);
    cudaGetSymbolAddress((void**)&Gh,   g_Gh);
    cudaGetSymbolAddress((void**)&Gl,   g_Gl);
    cudaGetSymbolAddress((void**)&Th,   g_Th);
    cudaGetSymbolAddress((void**)&Tl,   g_Tl);
    cudaGetSymbolAddress((void**)&Ahp,  g_Ah);
    cudaGetSymbolAddress((void**)&Alp,  g_Al);
    cudaGetSymbolAddress((void**)&Mh,   g_Mh);
    cudaGetSymbolAddress((void**)&Ml,   g_Ml);
    cudaGetSymbolAddress((void**)&S,    g_S);

    cudaFuncSetAttribute(gemm_bf16x2_nt,
                         cudaFuncAttributeMaxDynamicSharedMemorySize, SMEM_BYTES);

    const long long sX  = (long long)DIMC * NPTS;   // x / xT / out batch stride
    const long long sDD = (long long)DIMC * DIMC;
    const float inv_tau = (float)(1.0 / sqrt((double)DIMC));

    {
        dim3 gx(NPTS / 32, DIMC / 32, BATCH);
        split_bf16_kernel<<<gx, 256>>>(x, xh, xl, xTh, xTl, DIMC, NPTS, sX, sX, sX);
        dim3 gw(DIMC / 32, DIMC / 32, 1);
        split_bf16_kernel<<<gw, 256>>>(Wq, Wqh, Wql, nullptr, nullptr, DIMC, DIMC, 0, 0, 0);
        split_bf16_kernel<<<gw, 256>>>(Wk, Wkh, Wkl, nullptr, nullptr, DIMC, DIMC, 0, 0, 0);
        split_bf16_kernel<<<gw, 256>>>(Wv, nullptr, nullptr, WvTh, WvTl, DIMC, DIMC, 0, 0, 0);
    }

    dim3 gSq(DIMC / BN, DIMC / BM, BATCH);   // 4 x 4 x 16
    dim3 gOut(NPTS / BN, DIMC / BM, BATCH);  // 32 x 4 x 16

    // G[b] = x[b] . x[b]^T  -> split
    gemm_bf16x2_nt<<<gSq, 256, SMEM_BYTES>>>(xh, xl, xh, xl,
        nullptr, Gh, Gl,
        NPTS, NPTS, NPTS, 0, DIMC, sX, sX, 0LL, sDD, 1.0f);

    // T[b] = Wq . G[b]  (G symmetric) -> split
    gemm_bf16x2_nt<<<gSq, 256, SMEM_BYTES>>>(Wqh, Wql, Gh, Gl,
        nullptr, Th, Tl,
        DIMC, DIMC, DIMC, 0, DIMC, 0LL, sDD, 0LL, sDD, 1.0f);

    // S[b] = (1/tau) T[b] . Wk^T -> plain
    gemm_bf16x2_nt<<<gSq, 256, SMEM_BYTES>>>(Th, Tl, Wkh, Wkl,
        S, nullptr, nullptr,
        DIMC, DIMC, DIMC, DIMC, 0, sDD, 0LL, sDD, 0LL, inv_tau);

    // A = softmax(S) -> split
    softmax_split_kernel<<<BATCH * DIMC, 256>>>(S, Ahp, Alp);

    // M[b] = A[b] . Wv (B = WvT) -> split
    gemm_bf16x2_nt<<<gSq, 256, SMEM_BYTES>>>(Ahp, Alp, WvTh, WvTl,
        nullptr, Mh, Ml,
        DIMC, DIMC, DIMC, 0, DIMC, sDD, 0LL, 0LL, sDD, 1.0f);

    // out[b] = M[b] . x[b]  (B = xT) -> plain
    gemm_bf16x2_nt<<<gOut, 256, SMEM_BYTES>>>(Mh, Ml, xTh, xTl,
        out, nullptr, nullptr,
        DIMC, DIMC, DIMC, NPTS, 0, sDD, sX, sX, 0LL, 1.0f);
}